// round 1
// baseline (speedup 1.0000x reference)
#include <cuda_runtime.h>

#define NB   32
#define NN   4096
#define DM   64
#define NSUP 2

// scratch (allocation-free: device globals)
__device__ float g_y[NB * 2 * DM * NN];   // [b][s][o][v]  64 MB
__device__ float g_z[NB * DM * NN];       // [b][o][v]     32 MB

#define FMA2(d, a, bb) asm("fma.rn.f32x2 %0, %1, %2, %0;" : "+l"(d) : "l"(a), "l"(bb))

// ---------------------------------------------------------------------------
// Kernel A: y[b,s,o,v] = sum_c W_mlp[o, s*65+c] * xin[b,c,v]
// rows r = s*64+o (128 rows), v-tile 128 per block. K=65 in chunks of 13.
// ---------------------------------------------------------------------------
#define CH 13
__global__ __launch_bounds__(256) void kernA(const float* __restrict__ x,
                                             const float* __restrict__ h,
                                             const float* __restrict__ Wm)
{
    __shared__ float Xs[CH][128];
    __shared__ float Ws[CH][128];
    const int b   = blockIdx.y;
    const int v0  = blockIdx.x * 128;
    const int tid = threadIdx.x;
    const int ty  = tid >> 4, tx = tid & 15;

    float acc[8][8];
#pragma unroll
    for (int i = 0; i < 8; i++)
#pragma unroll
        for (int j = 0; j < 8; j++) acc[i][j] = 0.0f;

    for (int c0 = 0; c0 < 65; c0 += CH) {
        for (int idx = tid; idx < CH * 128; idx += 256) {
            int cc = idx >> 7, v = idx & 127;
            int c = c0 + cc;
            float val;
            if (c == 0) val = x[(size_t)b * NN + v0 + v];
            else        val = h[((size_t)b * DM + (c - 1)) * NN + v0 + v];
            Xs[cc][v] = val;
        }
        for (int idx = tid; idx < CH * 128; idx += 256) {
            int cc = idx >> 7, r = idx & 127;
            int s = r >> 6, o = r & 63;
            Ws[cc][r] = Wm[o * 130 + s * 65 + (c0 + cc)];
        }
        __syncthreads();
#pragma unroll
        for (int cc = 0; cc < CH; cc++) {
            float4 w0 = *(const float4*)&Ws[cc][ty * 8];
            float4 w1 = *(const float4*)&Ws[cc][ty * 8 + 4];
            float4 x0 = *(const float4*)&Xs[cc][tx * 8];
            float4 x1 = *(const float4*)&Xs[cc][tx * 8 + 4];
            float wf[8] = {w0.x, w0.y, w0.z, w0.w, w1.x, w1.y, w1.z, w1.w};
            float xf[8] = {x0.x, x0.y, x0.z, x0.w, x1.x, x1.y, x1.z, x1.w};
#pragma unroll
            for (int i = 0; i < 8; i++)
#pragma unroll
                for (int j = 0; j < 8; j++) acc[i][j] += wf[i] * xf[j];
        }
        __syncthreads();
    }
#pragma unroll
    for (int i = 0; i < 8; i++) {
        int r = ty * 8 + i;
        float* dst = &g_y[((size_t)b * 128 + r) * NN + v0 + tx * 8];
        *(float4*)dst       = make_float4(acc[i][0], acc[i][1], acc[i][2], acc[i][3]);
        *(float4*)(dst + 4) = make_float4(acc[i][4], acc[i][5], acc[i][6], acc[i][7]);
    }
}

// ---------------------------------------------------------------------------
// Kernel B: Z[b,o,w] = sum_s sum_v y[b,s,o,v] * adj[s,w,v]
// Block tile: M=64 (all o), N=128 w, K-tile 32. fp32x2 packed FMA inner loop.
// A stored duplicated in SMEM so no packing MOVs are needed.
// ---------------------------------------------------------------------------
__global__ __launch_bounds__(256) void kernB(const float* __restrict__ adj)
{
    __shared__ float As[32 * 132];   // [kk][128] : 64 m-values, each duplicated
    __shared__ float Bs[32 * 132];   // [kk][128 w]
    const int b   = blockIdx.y;
    const int w0  = blockIdx.x * 128;
    const int tid = threadIdx.x;
    const int ty  = tid >> 4, tx = tid & 15;

    unsigned long long acc[4][4];
#pragma unroll
    for (int i = 0; i < 4; i++)
#pragma unroll
        for (int j = 0; j < 4; j++) acc[i][j] = 0ull;

    const int oa = tid >> 2, kqa = tid & 3;   // A loader: 64 rows x (4x8 kk)
    const int wb = tid >> 1, kqb = tid & 1;   // B loader: 128 rows x (2x16 kk)

    const float* ap = As + ty * 8;
    const float* bp = Bs + tx * 8;

    for (int ks = 0; ks < 256; ks++) {
        const int s  = ks >> 7;
        const int k0 = (ks & 127) << 5;

        const float* ysrc = &g_y[((size_t)b * 128 + s * 64 + oa) * NN + k0 + kqa * 8];
        float4 a0 = *(const float4*)ysrc;
        float4 a1 = *(const float4*)(ysrc + 4);

        const float* bsrc = &adj[((size_t)s * NN + w0 + wb) * NN + k0 + kqb * 16];
        float4 b0 = *(const float4*)bsrc;
        float4 b1 = *(const float4*)(bsrc + 4);
        float4 b2 = *(const float4*)(bsrc + 8);
        float4 b3 = *(const float4*)(bsrc + 12);

        __syncthreads();
        {
            float2* d = (float2*)As;                 // float2 row stride = 66
            int r = kqa * 8;
            d[(r + 0) * 66 + oa] = make_float2(a0.x, a0.x);
            d[(r + 1) * 66 + oa] = make_float2(a0.y, a0.y);
            d[(r + 2) * 66 + oa] = make_float2(a0.z, a0.z);
            d[(r + 3) * 66 + oa] = make_float2(a0.w, a0.w);
            d[(r + 4) * 66 + oa] = make_float2(a1.x, a1.x);
            d[(r + 5) * 66 + oa] = make_float2(a1.y, a1.y);
            d[(r + 6) * 66 + oa] = make_float2(a1.z, a1.z);
            d[(r + 7) * 66 + oa] = make_float2(a1.w, a1.w);
        }
        {
            int r = kqb * 16;
            Bs[(r + 0)  * 132 + wb] = b0.x;  Bs[(r + 1)  * 132 + wb] = b0.y;
            Bs[(r + 2)  * 132 + wb] = b0.z;  Bs[(r + 3)  * 132 + wb] = b0.w;
            Bs[(r + 4)  * 132 + wb] = b1.x;  Bs[(r + 5)  * 132 + wb] = b1.y;
            Bs[(r + 6)  * 132 + wb] = b1.z;  Bs[(r + 7)  * 132 + wb] = b1.w;
            Bs[(r + 8)  * 132 + wb] = b2.x;  Bs[(r + 9)  * 132 + wb] = b2.y;
            Bs[(r + 10) * 132 + wb] = b2.z;  Bs[(r + 11) * 132 + wb] = b2.w;
            Bs[(r + 12) * 132 + wb] = b3.x;  Bs[(r + 13) * 132 + wb] = b3.y;
            Bs[(r + 14) * 132 + wb] = b3.z;  Bs[(r + 15) * 132 + wb] = b3.w;
        }
        __syncthreads();

#pragma unroll
        for (int kk = 0; kk < 32; kk++) {
            ulonglong2 a01 = *(const ulonglong2*)(ap + kk * 132);
            ulonglong2 a23 = *(const ulonglong2*)(ap + kk * 132 + 4);
            ulonglong2 b01 = *(const ulonglong2*)(bp + kk * 132);
            ulonglong2 b23 = *(const ulonglong2*)(bp + kk * 132 + 4);
            FMA2(acc[0][0], a01.x, b01.x); FMA2(acc[0][1], a01.x, b01.y);
            FMA2(acc[0][2], a01.x, b23.x); FMA2(acc[0][3], a01.x, b23.y);
            FMA2(acc[1][0], a01.y, b01.x); FMA2(acc[1][1], a01.y, b01.y);
            FMA2(acc[1][2], a01.y, b23.x); FMA2(acc[1][3], a01.y, b23.y);
            FMA2(acc[2][0], a23.x, b01.x); FMA2(acc[2][1], a23.x, b01.y);
            FMA2(acc[2][2], a23.x, b23.x); FMA2(acc[2][3], a23.x, b23.y);
            FMA2(acc[3][0], a23.y, b01.x); FMA2(acc[3][1], a23.y, b01.y);
            FMA2(acc[3][2], a23.y, b23.x); FMA2(acc[3][3], a23.y, b23.y);
        }
    }

#pragma unroll
    for (int i = 0; i < 4; i++) {
        int m = ty * 4 + i;
        union { unsigned long long u; float2 f; } u0, u1, u2, u3;
        u0.u = acc[i][0]; u1.u = acc[i][1]; u2.u = acc[i][2]; u3.u = acc[i][3];
        float* dst = &g_z[((size_t)b * DM + m) * NN + w0 + tx * 8];
        *(float4*)dst       = make_float4(u0.f.x, u0.f.y, u1.f.x, u1.f.y);
        *(float4*)(dst + 4) = make_float4(u2.f.x, u2.f.y, u3.f.x, u3.f.y);
    }
}

// ---------------------------------------------------------------------------
// Kernel C: fused epilogue.
// lin[o,v] = sum_k W_lin[o,k]*In[k,v] + b_lin[o], In = [Z+b_mlp ; h]
// p = PReLU(lin); out2 = [p ; h]; read = W_read . out2 + b_read
// d_out layout: read [32*4096] then out2 [32*128*4096]
// ---------------------------------------------------------------------------
__global__ __launch_bounds__(256) void kernC(const float* __restrict__ h,
                                             const float* __restrict__ Wl,
                                             const float* __restrict__ bl,
                                             const float* __restrict__ Wr,
                                             const float* __restrict__ br,
                                             const float* __restrict__ bm,
                                             const float* __restrict__ pa,
                                             float* __restrict__ out)
{
    __shared__ float In[32][132];
    __shared__ float Wt[32][68];
    __shared__ float wr_s[128];
    __shared__ float red[128];
    const int b   = blockIdx.y;
    const int v0  = blockIdx.x * 128;
    const int tid = threadIdx.x;
    const int ty  = tid >> 4, tx = tid & 15;

    if (tid < 128) { wr_s[tid] = Wr[tid]; red[tid] = 0.0f; }

    float acc[4][8];
#pragma unroll
    for (int i = 0; i < 4; i++) {
        float bv = bl[ty * 4 + i];
#pragma unroll
        for (int j = 0; j < 8; j++) acc[i][j] = bv;
    }
    const float slope = pa[0];

    for (int k0 = 0; k0 < 128; k0 += 32) {
        __syncthreads();
        for (int idx = tid; idx < 32 * 128; idx += 256) {
            int kk = idx >> 7, v = idx & 127;
            int k = k0 + kk;
            float val;
            if (k < 64) val = g_z[((size_t)b * DM + k) * NN + v0 + v] + bm[k];
            else        val = h[((size_t)b * DM + (k - 64)) * NN + v0 + v];
            In[kk][v] = val;
        }
        for (int idx = tid; idx < 32 * 64; idx += 256) {
            int kk = idx >> 6, o = idx & 63;
            Wt[kk][o] = Wl[o * 128 + k0 + kk];
        }
        __syncthreads();
#pragma unroll
        for (int kk = 0; kk < 32; kk++) {
            float4 wv = *(const float4*)&Wt[kk][ty * 4];
            float4 i0 = *(const float4*)&In[kk][tx * 8];
            float4 i1 = *(const float4*)&In[kk][tx * 8 + 4];
            float wf[4] = {wv.x, wv.y, wv.z, wv.w};
            float xf[8] = {i0.x, i0.y, i0.z, i0.w, i1.x, i1.y, i1.z, i1.w};
#pragma unroll
            for (int i = 0; i < 4; i++)
#pragma unroll
                for (int j = 0; j < 8; j++) acc[i][j] += wf[i] * xf[j];
        }
    }

    float part[8];
#pragma unroll
    for (int j = 0; j < 8; j++) part[j] = 0.0f;

    float* out2 = out + (size_t)NB * NN;   // 131072
#pragma unroll
    for (int i = 0; i < 4; i++) {
        int o = ty * 4 + i;
        float p[8];
        float wro = wr_s[o];
#pragma unroll
        for (int j = 0; j < 8; j++) {
            float v = acc[i][j];
            p[j] = (v >= 0.0f) ? v : slope * v;
            part[j] += wro * p[j];
        }
        float* dst = &out2[((size_t)b * 128 + o) * NN + v0 + tx * 8];
        *(float4*)dst       = make_float4(p[0], p[1], p[2], p[3]);
        *(float4*)(dst + 4) = make_float4(p[4], p[5], p[6], p[7]);

        const float* hsrc = &h[((size_t)b * DM + o) * NN + v0 + tx * 8];
        float4 h0 = *(const float4*)hsrc;
        float4 h1 = *(const float4*)(hsrc + 4);
        float hf[8] = {h0.x, h0.y, h0.z, h0.w, h1.x, h1.y, h1.z, h1.w};
        float wrh = wr_s[64 + o];
#pragma unroll
        for (int j = 0; j < 8; j++) part[j] += wrh * hf[j];
        float* dsth = &out2[((size_t)b * 128 + 64 + o) * NN + v0 + tx * 8];
        *(float4*)dsth       = h0;
        *(float4*)(dsth + 4) = h1;
    }

    __syncthreads();   // red[] zero + all writes ordered
#pragma unroll
    for (int j = 0; j < 8; j++) atomicAdd(&red[tx * 8 + j], part[j]);
    __syncthreads();
    if (tid < 128) out[(size_t)b * NN + v0 + tid] = red[tid] + br[0];
}

// ---------------------------------------------------------------------------
extern "C" void kernel_launch(void* const* d_in, const int* in_sizes, int n_in,
                              void* d_out, int out_size)
{
    const float* x   = (const float*)d_in[0];
    const float* h   = (const float*)d_in[1];
    const float* adj = (const float*)d_in[2];
    const float* Wm  = (const float*)d_in[3];
    const float* bm  = (const float*)d_in[4];
    const float* Wl  = (const float*)d_in[5];
    const float* bl  = (const float*)d_in[6];
    const float* Wr  = (const float*)d_in[7];
    const float* br  = (const float*)d_in[8];
    const float* pa  = (const float*)d_in[9];
    float* out = (float*)d_out;

    dim3 grid(NN / 128, NB);
    kernA<<<grid, 256>>>(x, h, Wm);
    kernB<<<grid, 256>>>(adj);
    kernC<<<grid, 256>>>(h, Wl, bl, Wr, br, bm, pa, out);
}

// round 4
// speedup vs baseline: 3.6212x; 3.6212x over previous
#include <cuda_runtime.h>
#include <cstdint>

#define NB   32
#define NN   4096
#define DM   64

// scratch (allocation-free: device globals)
__device__ float g_y[NB * 2 * DM * NN];   // [b][s*64+o][v]  64 MB
__device__ float g_z[NB * DM * NN];       // [b][o][w]       32 MB

__device__ __forceinline__ uint32_t f2tf(float f) {
    uint32_t r; asm("cvt.rn.tf32.f32 %0, %1;" : "=r"(r) : "f"(f)); return r;
}

#define MMA_TF32(c, a, b)                                                    \
    asm volatile("mma.sync.aligned.m16n8k8.row.col.f32.tf32.tf32.f32 "       \
                 "{%0,%1,%2,%3}, {%4,%5,%6,%7}, {%8,%9}, {%0,%1,%2,%3};"     \
                 : "+f"((c)[0]), "+f"((c)[1]), "+f"((c)[2]), "+f"((c)[3])    \
                 : "r"((a)[0]), "r"((a)[1]), "r"((a)[2]), "r"((a)[3]),       \
                   "r"((b)[0]), "r"((b)[1]))

// ---------------------------------------------------------------------------
// Kernel A: y[b, s*64+o, v] = sum_c W_mlp[o, s*65+c] * xin[b,c,v]
// ---------------------------------------------------------------------------
#define CH 13
__global__ __launch_bounds__(256) void kernA(const float* __restrict__ x,
                                             const float* __restrict__ h,
                                             const float* __restrict__ Wm)
{
    __shared__ float Xs[CH][128];
    __shared__ float Ws[CH][128];
    const int b   = blockIdx.y;
    const int v0  = blockIdx.x * 128;
    const int tid = threadIdx.x;
    const int ty  = tid >> 4, tx = tid & 15;

    float acc[8][8];
#pragma unroll
    for (int i = 0; i < 8; i++)
#pragma unroll
        for (int j = 0; j < 8; j++) acc[i][j] = 0.0f;

    for (int c0 = 0; c0 < 65; c0 += CH) {
        for (int idx = tid; idx < CH * 128; idx += 256) {
            int cc = idx >> 7, v = idx & 127;
            int c = c0 + cc;
            float val;
            if (c == 0) val = x[(size_t)b * NN + v0 + v];
            else        val = h[((size_t)b * DM + (c - 1)) * NN + v0 + v];
            Xs[cc][v] = val;
        }
        for (int idx = tid; idx < CH * 128; idx += 256) {
            int cc = idx >> 7, r = idx & 127;
            int s = r >> 6, o = r & 63;
            Ws[cc][r] = Wm[o * 130 + s * 65 + (c0 + cc)];
        }
        __syncthreads();
#pragma unroll
        for (int cc = 0; cc < CH; cc++) {
            float4 w0 = *(const float4*)&Ws[cc][ty * 8];
            float4 w1 = *(const float4*)&Ws[cc][ty * 8 + 4];
            float4 x0 = *(const float4*)&Xs[cc][tx * 8];
            float4 x1 = *(const float4*)&Xs[cc][tx * 8 + 4];
            float wf[8] = {w0.x, w0.y, w0.z, w0.w, w1.x, w1.y, w1.z, w1.w};
            float xf[8] = {x0.x, x0.y, x0.z, x0.w, x1.x, x1.y, x1.z, x1.w};
#pragma unroll
            for (int i = 0; i < 8; i++)
#pragma unroll
                for (int j = 0; j < 8; j++) acc[i][j] += wf[i] * xf[j];
        }
        __syncthreads();
    }
#pragma unroll
    for (int i = 0; i < 8; i++) {
        int r = ty * 8 + i;
        float* dst = &g_y[((size_t)b * 128 + r) * NN + v0 + tx * 8];
        *(float4*)dst       = make_float4(acc[i][0], acc[i][1], acc[i][2], acc[i][3]);
        *(float4*)(dst + 4) = make_float4(acc[i][4], acc[i][5], acc[i][6], acc[i][7]);
    }
}

// ---------------------------------------------------------------------------
// Kernel B (tf32 mma.sync): Z[m=(b,o), n=w] = sum_s sum_k y[m,s,k]*adj[s,n,k]
// CTA tile 128x128, K-tile 32, 8 warps (2x4), warp tile 64x32.
// SMEM pitch-36 padding -> conflict-free fragment LDS. Double-buffered.
// ---------------------------------------------------------------------------
#define PITCH 36
#define STAGE (128 * PITCH)

__global__ __launch_bounds__(256, 2) void kernB_mma(const float* __restrict__ adj)
{
    extern __shared__ uint32_t smb[];
    const int tid  = threadIdx.x;
    const int wid  = tid >> 5, lane = tid & 31;
    const int r    = lane >> 2, cc = lane & 3;
    const int wm   = wid & 1;
    const int wn   = wid >> 1;            // FIXED: 0..3 column quadrant
    const int w0   = blockIdx.x * 128;
    const int m0   = blockIdx.y * 128;

    float c[4][4][4];
#pragma unroll
    for (int i = 0; i < 4; i++)
#pragma unroll
        for (int j = 0; j < 4; j++)
#pragma unroll
            for (int q = 0; q < 4; q++) c[i][j][q] = 0.0f;

    const int lrow = tid >> 1;             // 0..127
    const int lk   = (tid & 1) * 16;       // 0 or 16
    const int m    = m0 + lrow;
    const int bq   = m >> 6, oq = m & 63;
    const size_t ybase = ((size_t)bq * 128 + oq) * NN;   // + s*64*NN
    const size_t abase = (size_t)(w0 + lrow) * NN;       // + s*NN*NN

    float4 rA[4], rB[4];

    auto ldgA = [&](int it) {
        const int s = it >> 7, k0 = (it & 127) << 5;
        const float4* p = (const float4*)(g_y + ybase + (size_t)s * 64 * NN + k0 + lk);
#pragma unroll
        for (int j = 0; j < 4; j++) rA[j] = p[j];
    };
    auto ldgB = [&](int it) {
        const int s = it >> 7, k0 = (it & 127) << 5;
        const float4* p = (const float4*)(adj + (size_t)s * NN * NN + abase + k0 + lk);
#pragma unroll
        for (int j = 0; j < 4; j++) rB[j] = p[j];
    };
    auto stsA = [&](uint32_t* As) {
        uint32_t* d = As + lrow * PITCH + lk;
#pragma unroll
        for (int j = 0; j < 4; j++) {
            uint4 t; t.x = f2tf(rA[j].x); t.y = f2tf(rA[j].y);
            t.z = f2tf(rA[j].z); t.w = f2tf(rA[j].w);
            *(uint4*)(d + j * 4) = t;
        }
    };
    auto stsB = [&](uint32_t* Bs) {
        uint32_t* d = Bs + lrow * PITCH + lk;
#pragma unroll
        for (int j = 0; j < 4; j++) {
            uint4 t; t.x = f2tf(rB[j].x); t.y = f2tf(rB[j].y);
            t.z = f2tf(rB[j].z); t.w = f2tf(rB[j].w);
            *(uint4*)(d + j * 4) = t;
        }
    };

    auto mma_half = [&](const uint32_t* As, const uint32_t* Bs, int kk0) {
#pragma unroll
        for (int kk = kk0; kk < kk0 + 2; kk++) {
            uint32_t a[4][4], bfr[4][2];
#pragma unroll
            for (int mi = 0; mi < 4; mi++) {
                const uint32_t* ap = As + (wm * 64 + mi * 16 + r) * PITCH + kk * 8 + cc;
                a[mi][0] = ap[0];
                a[mi][1] = ap[8 * PITCH];
                a[mi][2] = ap[4];
                a[mi][3] = ap[8 * PITCH + 4];
            }
#pragma unroll
            for (int ni = 0; ni < 4; ni++) {
                const uint32_t* bp = Bs + (wn * 32 + ni * 8 + r) * PITCH + kk * 8 + cc;
                bfr[ni][0] = bp[0];
                bfr[ni][1] = bp[4];
            }
#pragma unroll
            for (int mi = 0; mi < 4; mi++)
#pragma unroll
                for (int ni = 0; ni < 4; ni++)
                    MMA_TF32(c[mi][ni], a[mi], bfr[ni]);
        }
    };

    // prologue: stage 0
    ldgA(0); ldgB(0);
    stsA(smb); stsB(smb + STAGE);
    __syncthreads();

    for (int it = 0; it < 256; ++it) {
        const int cur = it & 1;
        uint32_t* Asc = smb + cur * 2 * STAGE;
        uint32_t* Bsc = Asc + STAGE;
        uint32_t* Asn = smb + (cur ^ 1) * 2 * STAGE;
        uint32_t* Bsn = Asn + STAGE;
        const bool more = (it + 1 < 256);

        if (more) ldgA(it + 1);
        mma_half(Asc, Bsc, 0);
        if (more) stsA(Asn);
        if (more) ldgB(it + 1);
        mma_half(Asc, Bsc, 2);
        if (more) stsB(Bsn);
        __syncthreads();
    }

    // epilogue: accum -> g_z  (m = (b,o) rows, n = w cols; float2 stores)
#pragma unroll
    for (int mi = 0; mi < 4; mi++) {
        const int mrow = m0 + wm * 64 + mi * 16 + r;
#pragma unroll
        for (int ni = 0; ni < 4; ni++) {
            const int col = w0 + wn * 32 + ni * 8 + cc * 2;
            *(float2*)&g_z[(size_t)mrow * NN + col] =
                make_float2(c[mi][ni][0], c[mi][ni][1]);
            *(float2*)&g_z[(size_t)(mrow + 8) * NN + col] =
                make_float2(c[mi][ni][2], c[mi][ni][3]);
        }
    }
}

// ---------------------------------------------------------------------------
// Kernel C: fused epilogue
// ---------------------------------------------------------------------------
__global__ __launch_bounds__(256) void kernC(const float* __restrict__ h,
                                             const float* __restrict__ Wl,
                                             const float* __restrict__ bl,
                                             const float* __restrict__ Wr,
                                             const float* __restrict__ br,
                                             const float* __restrict__ bm,
                                             const float* __restrict__ pa,
                                             float* __restrict__ out)
{
    __shared__ float In[32][132];
    __shared__ float Wt[32][68];
    __shared__ float wr_s[128];
    __shared__ float red[128];
    const int b   = blockIdx.y;
    const int v0  = blockIdx.x * 128;
    const int tid = threadIdx.x;
    const int ty  = tid >> 4, tx = tid & 15;

    if (tid < 128) { wr_s[tid] = Wr[tid]; red[tid] = 0.0f; }

    float acc[4][8];
#pragma unroll
    for (int i = 0; i < 4; i++) {
        float bv = bl[ty * 4 + i];
#pragma unroll
        for (int j = 0; j < 8; j++) acc[i][j] = bv;
    }
    const float slope = pa[0];

    for (int k0 = 0; k0 < 128; k0 += 32) {
        __syncthreads();
        for (int idx = tid; idx < 32 * 128; idx += 256) {
            int kk = idx >> 7, v = idx & 127;
            int k = k0 + kk;
            float val;
            if (k < 64) val = g_z[((size_t)b * DM + k) * NN + v0 + v] + bm[k];
            else        val = h[((size_t)b * DM + (k - 64)) * NN + v0 + v];
            In[kk][v] = val;
        }
        for (int idx = tid; idx < 32 * 64; idx += 256) {
            int kk = idx >> 6, o = idx & 63;
            Wt[kk][o] = Wl[o * 128 + k0 + kk];
        }
        __syncthreads();
#pragma unroll
        for (int kk = 0; kk < 32; kk++) {
            float4 wv = *(const float4*)&Wt[kk][ty * 4];
            float4 i0 = *(const float4*)&In[kk][tx * 8];
            float4 i1 = *(const float4*)&In[kk][tx * 8 + 4];
            float wf[4] = {wv.x, wv.y, wv.z, wv.w};
            float xf[8] = {i0.x, i0.y, i0.z, i0.w, i1.x, i1.y, i1.z, i1.w};
#pragma unroll
            for (int i = 0; i < 4; i++)
#pragma unroll
                for (int j = 0; j < 8; j++) acc[i][j] += wf[i] * xf[j];
        }
    }

    float part[8];
#pragma unroll
    for (int j = 0; j < 8; j++) part[j] = 0.0f;

    float* out2 = out + (size_t)NB * NN;
#pragma unroll
    for (int i = 0; i < 4; i++) {
        int o = ty * 4 + i;
        float p[8];
        float wro = wr_s[o];
#pragma unroll
        for (int j = 0; j < 8; j++) {
            float v = acc[i][j];
            p[j] = (v >= 0.0f) ? v : slope * v;
            part[j] += wro * p[j];
        }
        float* dst = &out2[((size_t)b * 128 + o) * NN + v0 + tx * 8];
        *(float4*)dst       = make_float4(p[0], p[1], p[2], p[3]);
        *(float4*)(dst + 4) = make_float4(p[4], p[5], p[6], p[7]);

        const float* hsrc = &h[((size_t)b * DM + o) * NN + v0 + tx * 8];
        float4 h0 = *(const float4*)hsrc;
        float4 h1 = *(const float4*)(hsrc + 4);
        float hf[8] = {h0.x, h0.y, h0.z, h0.w, h1.x, h1.y, h1.z, h1.w};
        float wrh = wr_s[64 + o];
#pragma unroll
        for (int j = 0; j < 8; j++) part[j] += wrh * hf[j];
        float* dsth = &out2[((size_t)b * 128 + 64 + o) * NN + v0 + tx * 8];
        *(float4*)dsth       = h0;
        *(float4*)(dsth + 4) = h1;
    }

    __syncthreads();
#pragma unroll
    for (int j = 0; j < 8; j++) atomicAdd(&red[tx * 8 + j], part[j]);
    __syncthreads();
    if (tid < 128) out[(size_t)b * NN + v0 + tid] = red[tid] + br[0];
}

// ---------------------------------------------------------------------------
extern "C" void kernel_launch(void* const* d_in, const int* in_sizes, int n_in,
                              void* d_out, int out_size)
{
    const float* x   = (const float*)d_in[0];
    const float* h   = (const float*)d_in[1];
    const float* adj = (const float*)d_in[2];
    const float* Wm  = (const float*)d_in[3];
    const float* bm  = (const float*)d_in[4];
    const float* Wl  = (const float*)d_in[5];
    const float* bl  = (const float*)d_in[6];
    const float* Wr  = (const float*)d_in[7];
    const float* br  = (const float*)d_in[8];
    const float* pa  = (const float*)d_in[9];
    float* out = (float*)d_out;

    static bool configured = false;
    if (!configured) {
        cudaFuncSetAttribute(kernB_mma,
                             cudaFuncAttributeMaxDynamicSharedMemorySize,
                             4 * STAGE * 4);
        configured = true;
    }

    dim3 gridA(NN / 128, NB);
    kernA<<<gridA, 256>>>(x, h, Wm);
    kernB_mma<<<dim3(NN / 128, 2048 / 128), 256, 4 * STAGE * 4>>>(adj);
    kernC<<<gridA, 256>>>(h, Wl, bl, Wr, br, bm, pa, out);
}

// round 6
// speedup vs baseline: 5.0253x; 1.3878x over previous
#include <cuda_runtime.h>
#include <cstdint>

#define NB   32
#define NN   4096
#define DM   64

// scratch (allocation-free: device globals)
__device__ uint32_t g_yb[NB * 2 * DM * (NN / 2)];  // y as packed bf16x2: [b][s*64+o][k/2]  32 MB
__device__ float    g_z[NB * DM * NN];             // [b][o][w]  32 MB

__device__ __forceinline__ uint32_t pack_bf16(float lo, float hi) {
    uint32_t r;
    asm("cvt.rn.bf16x2.f32 %0, %1, %2;" : "=r"(r) : "f"(hi), "f"(lo));
    return r;
}

#define MMA_BF16(c, a, b)                                                    \
    asm volatile("mma.sync.aligned.m16n8k16.row.col.f32.bf16.bf16.f32 "      \
                 "{%0,%1,%2,%3}, {%4,%5,%6,%7}, {%8,%9}, {%0,%1,%2,%3};"     \
                 : "+f"((c)[0]), "+f"((c)[1]), "+f"((c)[2]), "+f"((c)[3])    \
                 : "r"((a)[0]), "r"((a)[1]), "r"((a)[2]), "r"((a)[3]),       \
                   "r"((b)[0]), "r"((b)[1]))

// ---------------------------------------------------------------------------
// Kernel A: y[b, s*64+o, v] = sum_c W_mlp[o, s*65+c] * xin[b,c,v]  (bf16 out)
// ---------------------------------------------------------------------------
#define CH 13
__global__ __launch_bounds__(256) void kernA(const float* __restrict__ x,
                                             const float* __restrict__ h,
                                             const float* __restrict__ Wm)
{
    __shared__ float Xs[CH][128];
    __shared__ float Ws[CH][128];
    const int b   = blockIdx.y;
    const int v0  = blockIdx.x * 128;
    const int tid = threadIdx.x;
    const int ty  = tid >> 4, tx = tid & 15;

    float acc[8][8];
#pragma unroll
    for (int i = 0; i < 8; i++)
#pragma unroll
        for (int j = 0; j < 8; j++) acc[i][j] = 0.0f;

    for (int c0 = 0; c0 < 65; c0 += CH) {
        for (int idx = tid; idx < CH * 128; idx += 256) {
            int cc = idx >> 7, v = idx & 127;
            int c = c0 + cc;
            float val;
            if (c == 0) val = x[(size_t)b * NN + v0 + v];
            else        val = h[((size_t)b * DM + (c - 1)) * NN + v0 + v];
            Xs[cc][v] = val;
        }
        for (int idx = tid; idx < CH * 128; idx += 256) {
            int cc = idx >> 7, r = idx & 127;
            int s = r >> 6, o = r & 63;
            Ws[cc][r] = Wm[o * 130 + s * 65 + (c0 + cc)];
        }
        __syncthreads();
#pragma unroll
        for (int cc = 0; cc < CH; cc++) {
            float4 w0 = *(const float4*)&Ws[cc][ty * 8];
            float4 w1 = *(const float4*)&Ws[cc][ty * 8 + 4];
            float4 x0 = *(const float4*)&Xs[cc][tx * 8];
            float4 x1 = *(const float4*)&Xs[cc][tx * 8 + 4];
            float wf[8] = {w0.x, w0.y, w0.z, w0.w, w1.x, w1.y, w1.z, w1.w};
            float xf[8] = {x0.x, x0.y, x0.z, x0.w, x1.x, x1.y, x1.z, x1.w};
#pragma unroll
            for (int i = 0; i < 8; i++)
#pragma unroll
                for (int j = 0; j < 8; j++) acc[i][j] += wf[i] * xf[j];
        }
        __syncthreads();
    }
#pragma unroll
    for (int i = 0; i < 8; i++) {
        int r = ty * 8 + i;
        uint32_t* dst = &g_yb[((size_t)b * 128 + r) * (NN / 2) + (v0 >> 1) + tx * 4];
        uint4 t;
        t.x = pack_bf16(acc[i][0], acc[i][1]);
        t.y = pack_bf16(acc[i][2], acc[i][3]);
        t.z = pack_bf16(acc[i][4], acc[i][5]);
        t.w = pack_bf16(acc[i][6], acc[i][7]);
        *(uint4*)dst = t;
    }
}

// ---------------------------------------------------------------------------
// Kernel B (bf16 mma.sync m16n8k16): Z[m=(b,o), n=w] = sum_{s,k} y*adj
// CTA tile 128(m) x 128(w), K-tile 32 bf16, 8 warps (2x4), warp tile 64x32.
// SMEM u32 pitch-20 -> conflict-free fragment LDS. Double-buffered.
// Grid: x = m-tile (16), y = w-tile (32)  -> wave shares adj slice in L2.
// ---------------------------------------------------------------------------
#define PITCH 20
#define STAGE (128 * PITCH)

__global__ __launch_bounds__(256, 2) void kernB_mma(const float* __restrict__ adj)
{
    extern __shared__ uint32_t smb[];
    const int tid  = threadIdx.x;
    const int wid  = tid >> 5, lane = tid & 31;
    const int r    = lane >> 2, cc = lane & 3;
    const int wm   = wid & 1;
    const int wn   = wid >> 1;
    const int m0   = blockIdx.x * 128;
    const int w0   = blockIdx.y * 128;

    float c[4][4][4];
#pragma unroll
    for (int i = 0; i < 4; i++)
#pragma unroll
        for (int j = 0; j < 4; j++)
#pragma unroll
            for (int q = 0; q < 4; q++) c[i][j][q] = 0.0f;

    const int lrow = tid >> 1;             // 0..127
    const int half = tid & 1;              // 0/1
    const int m    = m0 + lrow;
    const int bq   = m >> 6, oq = m & 63;
    const size_t ybase = ((size_t)bq * 128 + oq) * (NN / 2);   // + s*64*(NN/2)
    const size_t abase = (size_t)(w0 + lrow) * NN;             // + s*NN*NN

    uint4  rA[2];
    float4 rB[4];

    auto ldgA = [&](int it) {
        const int s = it >> 7, ku = (it & 127) << 4;   // u32 offset
        const uint4* p = (const uint4*)(g_yb + ybase + (size_t)s * 64 * (NN / 2)
                                        + ku + half * 8);
        rA[0] = p[0]; rA[1] = p[1];
    };
    auto ldgB = [&](int it) {
        const int s = it >> 7, k0 = (it & 127) << 5;
        const float4* p = (const float4*)(adj + (size_t)s * NN * NN + abase
                                          + k0 + half * 16);
#pragma unroll
        for (int j = 0; j < 4; j++) rB[j] = p[j];
    };
    auto stsA = [&](uint32_t* As) {
        uint32_t* d = As + lrow * PITCH + half * 8;
        *(uint4*)d       = rA[0];
        *(uint4*)(d + 4) = rA[1];
    };
    auto stsB = [&](uint32_t* Bs) {
        uint32_t* d = Bs + lrow * PITCH + half * 8;
        uint4 t0, t1;
        t0.x = pack_bf16(rB[0].x, rB[0].y); t0.y = pack_bf16(rB[0].z, rB[0].w);
        t0.z = pack_bf16(rB[1].x, rB[1].y); t0.w = pack_bf16(rB[1].z, rB[1].w);
        t1.x = pack_bf16(rB[2].x, rB[2].y); t1.y = pack_bf16(rB[2].z, rB[2].w);
        t1.z = pack_bf16(rB[3].x, rB[3].y); t1.w = pack_bf16(rB[3].z, rB[3].w);
        *(uint4*)d       = t0;
        *(uint4*)(d + 4) = t1;
    };

    auto mma_tile = [&](const uint32_t* As, const uint32_t* Bs) {
#pragma unroll
        for (int kk = 0; kk < 2; kk++) {       // two k16 steps
            uint32_t a[4][4], bfr[4][2];
#pragma unroll
            for (int mi = 0; mi < 4; mi++) {
                const uint32_t* ap = As + (wm * 64 + mi * 16 + r) * PITCH + kk * 8 + cc;
                a[mi][0] = ap[0];
                a[mi][1] = ap[8 * PITCH];
                a[mi][2] = ap[4];
                a[mi][3] = ap[8 * PITCH + 4];
            }
#pragma unroll
            for (int ni = 0; ni < 4; ni++) {
                const uint32_t* bp = Bs + (wn * 32 + ni * 8 + r) * PITCH + kk * 8 + cc;
                bfr[ni][0] = bp[0];
                bfr[ni][1] = bp[4];
            }
#pragma unroll
            for (int mi = 0; mi < 4; mi++)
#pragma unroll
                for (int ni = 0; ni < 4; ni++)
                    MMA_BF16(c[mi][ni], a[mi], bfr[ni]);
        }
    };

    // prologue: stage 0
    ldgA(0); ldgB(0);
    stsA(smb); stsB(smb + STAGE);
    __syncthreads();

    for (int it = 0; it < 256; ++it) {
        const int cur = it & 1;
        uint32_t* Asc = smb + cur * 2 * STAGE;
        uint32_t* Bsc = Asc + STAGE;
        uint32_t* Asn = smb + (cur ^ 1) * 2 * STAGE;
        uint32_t* Bsn = Asn + STAGE;
        const bool more = (it + 1 < 256);

        if (more) { ldgA(it + 1); ldgB(it + 1); }
        mma_tile(Asc, Bsc);
        if (more) { stsA(Asn); stsB(Bsn); }
        __syncthreads();
    }

    // epilogue: accum -> g_z
#pragma unroll
    for (int mi = 0; mi < 4; mi++) {
        const int mrow = m0 + wm * 64 + mi * 16 + r;
#pragma unroll
        for (int ni = 0; ni < 4; ni++) {
            const int col = w0 + wn * 32 + ni * 8 + cc * 2;
            *(float2*)&g_z[(size_t)mrow * NN + col] =
                make_float2(c[mi][ni][0], c[mi][ni][1]);
            *(float2*)&g_z[(size_t)(mrow + 8) * NN + col] =
                make_float2(c[mi][ni][2], c[mi][ni][3]);
        }
    }
}

// ---------------------------------------------------------------------------
// Kernel C: fused epilogue
// ---------------------------------------------------------------------------
__global__ __launch_bounds__(256) void kernC(const float* __restrict__ h,
                                             const float* __restrict__ Wl,
                                             const float* __restrict__ bl,
                                             const float* __restrict__ Wr,
                                             const float* __restrict__ br,
                                             const float* __restrict__ bm,
                                             const float* __restrict__ pa,
                                             float* __restrict__ out)
{
    __shared__ float In[32][132];
    __shared__ float Wt[32][68];
    __shared__ float wr_s[128];
    __shared__ float red[128];
    const int b   = blockIdx.y;
    const int v0  = blockIdx.x * 128;
    const int tid = threadIdx.x;
    const int ty  = tid >> 4, tx = tid & 15;

    if (tid < 128) { wr_s[tid] = Wr[tid]; red[tid] = 0.0f; }

    float acc[4][8];
#pragma unroll
    for (int i = 0; i < 4; i++) {
        float bv = bl[ty * 4 + i];
#pragma unroll
        for (int j = 0; j < 8; j++) acc[i][j] = bv;
    }
    const float slope = pa[0];

    for (int k0 = 0; k0 < 128; k0 += 32) {
        __syncthreads();
        for (int idx = tid; idx < 32 * 128; idx += 256) {
            int kk = idx >> 7, v = idx & 127;
            int k = k0 + kk;
            float val;
            if (k < 64) val = g_z[((size_t)b * DM + k) * NN + v0 + v] + bm[k];
            else        val = h[((size_t)b * DM + (k - 64)) * NN + v0 + v];
            In[kk][v] = val;
        }
        for (int idx = tid; idx < 32 * 64; idx += 256) {
            int kk = idx >> 6, o = idx & 63;
            Wt[kk][o] = Wl[o * 128 + k0 + kk];
        }
        __syncthreads();
#pragma unroll
        for (int kk = 0; kk < 32; kk++) {
            float4 wv = *(const float4*)&Wt[kk][ty * 4];
            float4 i0 = *(const float4*)&In[kk][tx * 8];
            float4 i1 = *(const float4*)&In[kk][tx * 8 + 4];
            float wf[4] = {wv.x, wv.y, wv.z, wv.w};
            float xf[8] = {i0.x, i0.y, i0.z, i0.w, i1.x, i1.y, i1.z, i1.w};
#pragma unroll
            for (int i = 0; i < 4; i++)
#pragma unroll
                for (int j = 0; j < 8; j++) acc[i][j] += wf[i] * xf[j];
        }
    }

    float part[8];
#pragma unroll
    for (int j = 0; j < 8; j++) part[j] = 0.0f;

    float* out2 = out + (size_t)NB * NN;
#pragma unroll
    for (int i = 0; i < 4; i++) {
        int o = ty * 4 + i;
        float p[8];
        float wro = wr_s[o];
#pragma unroll
        for (int j = 0; j < 8; j++) {
            float v = acc[i][j];
            p[j] = (v >= 0.0f) ? v : slope * v;
            part[j] += wro * p[j];
        }
        float* dst = &out2[((size_t)b * 128 + o) * NN + v0 + tx * 8];
        *(float4*)dst       = make_float4(p[0], p[1], p[2], p[3]);
        *(float4*)(dst + 4) = make_float4(p[4], p[5], p[6], p[7]);

        const float* hsrc = &h[((size_t)b * DM + o) * NN + v0 + tx * 8];
        float4 h0 = *(const float4*)hsrc;
        float4 h1 = *(const float4*)(hsrc + 4);
        float hf[8] = {h0.x, h0.y, h0.z, h0.w, h1.x, h1.y, h1.z, h1.w};
        float wrh = wr_s[64 + o];
#pragma unroll
        for (int j = 0; j < 8; j++) part[j] += wrh * hf[j];
        float* dsth = &out2[((size_t)b * 128 + 64 + o) * NN + v0 + tx * 8];
        *(float4*)dsth       = h0;
        *(float4*)(dsth + 4) = h1;
    }

    __syncthreads();
#pragma unroll
    for (int j = 0; j < 8; j++) atomicAdd(&red[tx * 8 + j], part[j]);
    __syncthreads();
    if (tid < 128) out[(size_t)b * NN + v0 + tid] = red[tid] + br[0];
}

// ---------------------------------------------------------------------------
extern "C" void kernel_launch(void* const* d_in, const int* in_sizes, int n_in,
                              void* d_out, int out_size)
{
    const float* x   = (const float*)d_in[0];
    const float* h   = (const float*)d_in[1];
    const float* adj = (const float*)d_in[2];
    const float* Wm  = (const float*)d_in[3];
    const float* bm  = (const float*)d_in[4];
    const float* Wl  = (const float*)d_in[5];
    const float* bl  = (const float*)d_in[6];
    const float* Wr  = (const float*)d_in[7];
    const float* br  = (const float*)d_in[8];
    const float* pa  = (const float*)d_in[9];
    float* out = (float*)d_out;

    dim3 gridA(NN / 128, NB);
    kernA<<<gridA, 256>>>(x, h, Wm);
    kernB_mma<<<dim3(2048 / 128, NN / 128), 256, 4 * STAGE * 4>>>(adj);
    kernC<<<gridA, 256>>>(h, Wl, bl, Wr, br, bm, pa, out);
}

// round 7
// speedup vs baseline: 7.9449x; 1.5810x over previous
#include <cuda_runtime.h>
#include <cstdint>

#define NB   32
#define NN   4096
#define DM   64

// scratch (allocation-free: device globals)
__device__ uint32_t g_yb[NB * 2 * DM * (NN / 2)];  // y bf16x2: [b][s*64+o][k/2]  32 MB
__device__ uint32_t g_ab[2 * NN * (NN / 2)];       // adj bf16x2: [s][w][k/2]     67 MB
__device__ float    g_z[NB * DM * NN];             // [b][o][w]                   32 MB

__device__ __forceinline__ uint32_t pack_bf16(float lo, float hi) {
    uint32_t r;
    asm("cvt.rn.bf16x2.f32 %0, %1, %2;" : "=r"(r) : "f"(hi), "f"(lo));
    return r;
}

#define MMA_BF16(c, a, b)                                                    \
    asm volatile("mma.sync.aligned.m16n8k16.row.col.f32.bf16.bf16.f32 "      \
                 "{%0,%1,%2,%3}, {%4,%5,%6,%7}, {%8,%9}, {%0,%1,%2,%3};"     \
                 : "+f"((c)[0]), "+f"((c)[1]), "+f"((c)[2]), "+f"((c)[3])    \
                 : "r"((a)[0]), "r"((a)[1]), "r"((a)[2]), "r"((a)[3]),       \
                   "r"((b)[0]), "r"((b)[1]))

#define LDSM_X4(r0, r1, r2, r3, addr)                                        \
    asm volatile("ldmatrix.sync.aligned.m8n8.x4.shared.b16 {%0,%1,%2,%3}, [%4];" \
                 : "=r"(r0), "=r"(r1), "=r"(r2), "=r"(r3) : "r"(addr))

#define CP_ASYNC16(dst, src)                                                 \
    asm volatile("cp.async.cg.shared.global [%0], [%1], 16;"                 \
                 :: "r"(dst), "l"(src) : "memory")
#define CP_COMMIT()  asm volatile("cp.async.commit_group;" ::: "memory")
#define CP_WAIT1()   asm volatile("cp.async.wait_group 1;" ::: "memory")

// ---------------------------------------------------------------------------
// Kernel P: adj float -> bf16 (g_ab)
// ---------------------------------------------------------------------------
__global__ __launch_bounds__(256) void kernP(const float* __restrict__ adj)
{
    const size_t u = ((size_t)blockIdx.x * 256 + threadIdx.x) * 4;  // u32 index
    const float4* s = (const float4*)(adj + u * 2);
    float4 v0 = s[0], v1 = s[1];
    uint4 t;
    t.x = pack_bf16(v0.x, v0.y); t.y = pack_bf16(v0.z, v0.w);
    t.z = pack_bf16(v1.x, v1.y); t.w = pack_bf16(v1.z, v1.w);
    *(uint4*)(g_ab + u) = t;
}

// ---------------------------------------------------------------------------
// Kernel A: y[b, s*64+o, v] = sum_c W_mlp[o, s*65+c] * xin[b,c,v]  (bf16 out)
// ---------------------------------------------------------------------------
#define CH 13
__global__ __launch_bounds__(256) void kernA(const float* __restrict__ x,
                                             const float* __restrict__ h,
                                             const float* __restrict__ Wm)
{
    __shared__ float Xs[CH][128];
    __shared__ float Ws[CH][128];
    const int b   = blockIdx.y;
    const int v0  = blockIdx.x * 128;
    const int tid = threadIdx.x;
    const int ty  = tid >> 4, tx = tid & 15;

    float acc[8][8];
#pragma unroll
    for (int i = 0; i < 8; i++)
#pragma unroll
        for (int j = 0; j < 8; j++) acc[i][j] = 0.0f;

    for (int c0 = 0; c0 < 65; c0 += CH) {
        for (int idx = tid; idx < CH * 128; idx += 256) {
            int cc = idx >> 7, v = idx & 127;
            int c = c0 + cc;
            float val;
            if (c == 0) val = x[(size_t)b * NN + v0 + v];
            else        val = h[((size_t)b * DM + (c - 1)) * NN + v0 + v];
            Xs[cc][v] = val;
        }
        for (int idx = tid; idx < CH * 128; idx += 256) {
            int cc = idx >> 7, r = idx & 127;
            int s = r >> 6, o = r & 63;
            Ws[cc][r] = Wm[o * 130 + s * 65 + (c0 + cc)];
        }
        __syncthreads();
#pragma unroll
        for (int cc = 0; cc < CH; cc++) {
            float4 w0 = *(const float4*)&Ws[cc][ty * 8];
            float4 w1 = *(const float4*)&Ws[cc][ty * 8 + 4];
            float4 x0 = *(const float4*)&Xs[cc][tx * 8];
            float4 x1 = *(const float4*)&Xs[cc][tx * 8 + 4];
            float wf[8] = {w0.x, w0.y, w0.z, w0.w, w1.x, w1.y, w1.z, w1.w};
            float xf[8] = {x0.x, x0.y, x0.z, x0.w, x1.x, x1.y, x1.z, x1.w};
#pragma unroll
            for (int i = 0; i < 8; i++)
#pragma unroll
                for (int j = 0; j < 8; j++) acc[i][j] += wf[i] * xf[j];
        }
        __syncthreads();
    }
#pragma unroll
    for (int i = 0; i < 8; i++) {
        int r = ty * 8 + i;
        uint32_t* dst = &g_yb[((size_t)b * 128 + r) * (NN / 2) + (v0 >> 1) + tx * 4];
        uint4 t;
        t.x = pack_bf16(acc[i][0], acc[i][1]);
        t.y = pack_bf16(acc[i][2], acc[i][3]);
        t.z = pack_bf16(acc[i][4], acc[i][5]);
        t.w = pack_bf16(acc[i][6], acc[i][7]);
        *(uint4*)dst = t;
    }
}

// ---------------------------------------------------------------------------
// Kernel B: bf16 mma + cp.async 3-stage + ldmatrix.
// Z[m=(b,o), n=w] = sum_{s,k} y[m,s,k]*adj[s,n,k]
// CTA 128x128, K-tile 32. 8 warps (2 m-halves x 4 n-quarters), warp 64x32.
// SMEM u32 pitch-20 rows (16B-aligned, ldmatrix/cp.async conflict-free).
// ---------------------------------------------------------------------------
#define PITCH   20
#define OPER    (128 * PITCH)         // u32 per operand per stage (2560)
#define STAGEU  (2 * OPER)            // u32 per stage (5120)
#define NSTAGE  3
#define SMEMB   (NSTAGE * STAGEU * 4) // 61440 bytes

__global__ __launch_bounds__(256, 2) void kernB_mma()
{
    extern __shared__ uint32_t smb[];
    const uint32_t smem0 = (uint32_t)__cvta_generic_to_shared(smb);

    const int tid  = threadIdx.x;
    const int wid  = tid >> 5, lane = tid & 31;
    const int wm   = wid & 1;
    const int wn   = wid >> 1;
    const int m0   = blockIdx.x * 128;
    const int w0   = blockIdx.y * 128;

    float c[4][4][4];
#pragma unroll
    for (int i = 0; i < 4; i++)
#pragma unroll
        for (int j = 0; j < 4; j++)
#pragma unroll
            for (int q = 0; q < 4; q++) c[i][j][q] = 0.0f;

    // ---- loader constants: 512 16B-chunks per operand, 2 per thread ----
    const int lr  = tid >> 2;            // row 0..63 (and +64)
    const int ci  = tid & 3;             // 16B chunk in row
    // A rows: m = m0 + row
    const int mA0 = m0 + lr,       mA1 = m0 + lr + 64;
    const size_t yb0 = ((size_t)(mA0 >> 6) * 128 + (mA0 & 63)) * (NN / 2) + ci * 4;
    const size_t yb1 = ((size_t)(mA1 >> 6) * 128 + (mA1 & 63)) * (NN / 2) + ci * 4;
    // B rows: w = w0 + row
    const size_t ab0 = (size_t)(w0 + lr) * (NN / 2) + ci * 4;
    const size_t ab1 = (size_t)(w0 + lr + 64) * (NN / 2) + ci * 4;
    // dst u32 offsets (within stage)
    const uint32_t dA0 = lr * PITCH + ci * 4, dA1 = (lr + 64) * PITCH + ci * 4;

    auto issue_stage = [&](int it, int st) {
        const int s   = it >> 7;
        const int k0u = (it & 127) << 4;            // u32 offset along k
        const size_t ys = (size_t)s * 64 * (NN / 2) + k0u;
        const size_t as = (size_t)s * NN * (NN / 2) + k0u;
        const uint32_t base = smem0 + st * (STAGEU * 4);
        CP_ASYNC16(base + dA0 * 4,              (const void*)(g_yb + yb0 + ys));
        CP_ASYNC16(base + dA1 * 4,              (const void*)(g_yb + yb1 + ys));
        CP_ASYNC16(base + (OPER + dA0) * 4,     (const void*)(g_ab + ab0 + as));
        CP_ASYNC16(base + (OPER + dA1) * 4,     (const void*)(g_ab + ab1 + as));
    };

    // ---- ldmatrix lane offsets (u32) ----
    const uint32_t aoff = (uint32_t)((wm * 64 + (lane & 15)) * PITCH + (lane >> 4) * 4);
    const int bt   = lane >> 3;
    const uint32_t boff = (uint32_t)((wn * 32 + (lane & 7) + ((bt >> 1) * 8)) * PITCH
                                     + (bt & 1) * 4);

    // prologue: stages 0, 1
    issue_stage(0, 0); CP_COMMIT();
    issue_stage(1, 1); CP_COMMIT();

    for (int it = 0; it < 256; ++it) {
        CP_WAIT1();
        __syncthreads();
        if (it + 2 < 256) issue_stage(it + 2, (it + 2) % NSTAGE);
        CP_COMMIT();

        const uint32_t Ab = smem0 + (it % NSTAGE) * (STAGEU * 4);
        const uint32_t Bb = Ab + OPER * 4;

#pragma unroll
        for (int kk = 0; kk < 2; kk++) {
            uint32_t a[4][4], bfr[4][2];
#pragma unroll
            for (int mi = 0; mi < 4; mi++) {
                uint32_t ad = Ab + (aoff + mi * 16 * PITCH + kk * 8) * 4;
                LDSM_X4(a[mi][0], a[mi][1], a[mi][2], a[mi][3], ad);
            }
#pragma unroll
            for (int nj = 0; nj < 2; nj++) {
                uint32_t bd = Bb + (boff + nj * 16 * PITCH + kk * 8) * 4;
                LDSM_X4(bfr[nj * 2][0], bfr[nj * 2][1],
                        bfr[nj * 2 + 1][0], bfr[nj * 2 + 1][1], bd);
            }
#pragma unroll
            for (int mi = 0; mi < 4; mi++)
#pragma unroll
                for (int ni = 0; ni < 4; ni++)
                    MMA_BF16(c[mi][ni], a[mi], bfr[ni]);
        }
    }

    // epilogue: accum -> g_z
    const int r  = lane >> 2, cc = lane & 3;
#pragma unroll
    for (int mi = 0; mi < 4; mi++) {
        const int mrow = m0 + wm * 64 + mi * 16 + r;
#pragma unroll
        for (int ni = 0; ni < 4; ni++) {
            const int col = w0 + wn * 32 + ni * 8 + cc * 2;
            *(float2*)&g_z[(size_t)mrow * NN + col] =
                make_float2(c[mi][ni][0], c[mi][ni][1]);
            *(float2*)&g_z[(size_t)(mrow + 8) * NN + col] =
                make_float2(c[mi][ni][2], c[mi][ni][3]);
        }
    }
}

// ---------------------------------------------------------------------------
// Kernel C: fused epilogue
// ---------------------------------------------------------------------------
__global__ __launch_bounds__(256) void kernC(const float* __restrict__ h,
                                             const float* __restrict__ Wl,
                                             const float* __restrict__ bl,
                                             const float* __restrict__ Wr,
                                             const float* __restrict__ br,
                                             const float* __restrict__ bm,
                                             const float* __restrict__ pa,
                                             float* __restrict__ out)
{
    __shared__ float In[32][132];
    __shared__ float Wt[32][68];
    __shared__ float wr_s[128];
    __shared__ float red[128];
    const int b   = blockIdx.y;
    const int v0  = blockIdx.x * 128;
    const int tid = threadIdx.x;
    const int ty  = tid >> 4, tx = tid & 15;

    if (tid < 128) { wr_s[tid] = Wr[tid]; red[tid] = 0.0f; }

    float acc[4][8];
#pragma unroll
    for (int i = 0; i < 4; i++) {
        float bv = bl[ty * 4 + i];
#pragma unroll
        for (int j = 0; j < 8; j++) acc[i][j] = bv;
    }
    const float slope = pa[0];

    for (int k0 = 0; k0 < 128; k0 += 32) {
        __syncthreads();
        for (int idx = tid; idx < 32 * 128; idx += 256) {
            int kk = idx >> 7, v = idx & 127;
            int k = k0 + kk;
            float val;
            if (k < 64) val = g_z[((size_t)b * DM + k) * NN + v0 + v] + bm[k];
            else        val = h[((size_t)b * DM + (k - 64)) * NN + v0 + v];
            In[kk][v] = val;
        }
        for (int idx = tid; idx < 32 * 64; idx += 256) {
            int kk = idx >> 6, o = idx & 63;
            Wt[kk][o] = Wl[o * 128 + k0 + kk];
        }
        __syncthreads();
#pragma unroll
        for (int kk = 0; kk < 32; kk++) {
            float4 wv = *(const float4*)&Wt[kk][ty * 4];
            float4 i0 = *(const float4*)&In[kk][tx * 8];
            float4 i1 = *(const float4*)&In[kk][tx * 8 + 4];
            float wf[4] = {wv.x, wv.y, wv.z, wv.w};
            float xf[8] = {i0.x, i0.y, i0.z, i0.w, i1.x, i1.y, i1.z, i1.w};
#pragma unroll
            for (int i = 0; i < 4; i++)
#pragma unroll
                for (int j = 0; j < 8; j++) acc[i][j] += wf[i] * xf[j];
        }
    }

    float part[8];
#pragma unroll
    for (int j = 0; j < 8; j++) part[j] = 0.0f;

    float* out2 = out + (size_t)NB * NN;
#pragma unroll
    for (int i = 0; i < 4; i++) {
        int o = ty * 4 + i;
        float p[8];
        float wro = wr_s[o];
#pragma unroll
        for (int j = 0; j < 8; j++) {
            float v = acc[i][j];
            p[j] = (v >= 0.0f) ? v : slope * v;
            part[j] += wro * p[j];
        }
        float* dst = &out2[((size_t)b * 128 + o) * NN + v0 + tx * 8];
        *(float4*)dst       = make_float4(p[0], p[1], p[2], p[3]);
        *(float4*)(dst + 4) = make_float4(p[4], p[5], p[6], p[7]);

        const float* hsrc = &h[((size_t)b * DM + o) * NN + v0 + tx * 8];
        float4 h0 = *(const float4*)hsrc;
        float4 h1 = *(const float4*)(hsrc + 4);
        float hf[8] = {h0.x, h0.y, h0.z, h0.w, h1.x, h1.y, h1.z, h1.w};
        float wrh = wr_s[64 + o];
#pragma unroll
        for (int j = 0; j < 8; j++) part[j] += wrh * hf[j];
        float* dsth = &out2[((size_t)b * 128 + 64 + o) * NN + v0 + tx * 8];
        *(float4*)dsth       = h0;
        *(float4*)(dsth + 4) = h1;
    }

    __syncthreads();
#pragma unroll
    for (int j = 0; j < 8; j++) atomicAdd(&red[tx * 8 + j], part[j]);
    __syncthreads();
    if (tid < 128) out[(size_t)b * NN + v0 + tid] = red[tid] + br[0];
}

// ---------------------------------------------------------------------------
extern "C" void kernel_launch(void* const* d_in, const int* in_sizes, int n_in,
                              void* d_out, int out_size)
{
    const float* x   = (const float*)d_in[0];
    const float* h   = (const float*)d_in[1];
    const float* adj = (const float*)d_in[2];
    const float* Wm  = (const float*)d_in[3];
    const float* bm  = (const float*)d_in[4];
    const float* Wl  = (const float*)d_in[5];
    const float* bl  = (const float*)d_in[6];
    const float* Wr  = (const float*)d_in[7];
    const float* br  = (const float*)d_in[8];
    const float* pa  = (const float*)d_in[9];
    float* out = (float*)d_out;

    cudaFuncSetAttribute(kernB_mma, cudaFuncAttributeMaxDynamicSharedMemorySize, SMEMB);

    dim3 gridA(NN / 128, NB);
    kernP<<<2 * NN * (NN / 2) / (256 * 4), 256>>>(adj);
    kernA<<<gridA, 256>>>(x, h, Wm);
    kernB_mma<<<dim3(2048 / 128, NN / 128), 256, SMEMB>>>();
    kernC<<<gridA, 256>>>(h, Wl, bl, Wr, br, bm, pa, out);
}

// round 9
// speedup vs baseline: 8.7598x; 1.1026x over previous
#include <cuda_runtime.h>
#include <cstdint>

#define NB   32
#define NN   4096
#define DM   64

// scratch (allocation-free: device globals)
__device__ uint32_t g_yb[NB * 2 * DM * (NN / 2)];  // y bf16x2: [b][s*64+o][k/2]  32 MB
__device__ uint32_t g_ab[2 * NN * (NN / 2)];       // adj bf16x2: [s][w][k/2]     67 MB

__device__ __forceinline__ uint32_t pack_bf16(float lo, float hi) {
    uint32_t r;
    asm("cvt.rn.bf16x2.f32 %0, %1, %2;" : "=r"(r) : "f"(hi), "f"(lo));
    return r;
}

#define MMA_BF16(c, a, b)                                                    \
    asm volatile("mma.sync.aligned.m16n8k16.row.col.f32.bf16.bf16.f32 "      \
                 "{%0,%1,%2,%3}, {%4,%5,%6,%7}, {%8,%9}, {%0,%1,%2,%3};"     \
                 : "+f"((c)[0]), "+f"((c)[1]), "+f"((c)[2]), "+f"((c)[3])    \
                 : "r"((a)[0]), "r"((a)[1]), "r"((a)[2]), "r"((a)[3]),       \
                   "r"((b)[0]), "r"((b)[1]))

#define LDSM_X4(r0, r1, r2, r3, addr)                                        \
    asm volatile("ldmatrix.sync.aligned.m8n8.x4.shared.b16 {%0,%1,%2,%3}, [%4];" \
                 : "=r"(r0), "=r"(r1), "=r"(r2), "=r"(r3) : "r"(addr))

#define CP_ASYNC16(dst, src)                                                 \
    asm volatile("cp.async.cg.shared.global [%0], [%1], 16;"                 \
                 :: "r"(dst), "l"(src) : "memory")
#define CP_COMMIT()  asm volatile("cp.async.commit_group;" ::: "memory")
#define CP_WAIT3()   asm volatile("cp.async.wait_group 3;" ::: "memory")

// ---------------------------------------------------------------------------
// Kernel P: adj float -> bf16 (g_ab)
// ---------------------------------------------------------------------------
__global__ __launch_bounds__(256) void kernP(const float* __restrict__ adj)
{
    const size_t u = ((size_t)blockIdx.x * 256 + threadIdx.x) * 4;
    const float4* s = (const float4*)(adj + u * 2);
    float4 v0 = s[0], v1 = s[1];
    uint4 t;
    t.x = pack_bf16(v0.x, v0.y); t.y = pack_bf16(v0.z, v0.w);
    t.z = pack_bf16(v1.x, v1.y); t.w = pack_bf16(v1.z, v1.w);
    *(uint4*)(g_ab + u) = t;
}

// ---------------------------------------------------------------------------
// Kernel A: y[b, s*64+o, v] = sum_c W_mlp[o, s*65+c] * xin[b,c,v]  (bf16 out)
// ---------------------------------------------------------------------------
#define CH 13
__global__ __launch_bounds__(256) void kernA(const float* __restrict__ x,
                                             const float* __restrict__ h,
                                             const float* __restrict__ Wm)
{
    __shared__ float Xs[CH][128];
    __shared__ float Ws[CH][128];
    const int b   = blockIdx.y;
    const int v0  = blockIdx.x * 128;
    const int tid = threadIdx.x;
    const int ty  = tid >> 4, tx = tid & 15;

    float acc[8][8];
#pragma unroll
    for (int i = 0; i < 8; i++)
#pragma unroll
        for (int j = 0; j < 8; j++) acc[i][j] = 0.0f;

    for (int c0 = 0; c0 < 65; c0 += CH) {
        for (int idx = tid; idx < CH * 128; idx += 256) {
            int cc = idx >> 7, v = idx & 127;
            int c = c0 + cc;
            float val;
            if (c == 0) val = x[(size_t)b * NN + v0 + v];
            else        val = h[((size_t)b * DM + (c - 1)) * NN + v0 + v];
            Xs[cc][v] = val;
        }
        for (int idx = tid; idx < CH * 128; idx += 256) {
            int cc = idx >> 7, r = idx & 127;
            int s = r >> 6, o = r & 63;
            Ws[cc][r] = Wm[o * 130 + s * 65 + (c0 + cc)];
        }
        __syncthreads();
#pragma unroll
        for (int cc = 0; cc < CH; cc++) {
            float4 w0 = *(const float4*)&Ws[cc][ty * 8];
            float4 w1 = *(const float4*)&Ws[cc][ty * 8 + 4];
            float4 x0 = *(const float4*)&Xs[cc][tx * 8];
            float4 x1 = *(const float4*)&Xs[cc][tx * 8 + 4];
            float wf[8] = {w0.x, w0.y, w0.z, w0.w, w1.x, w1.y, w1.z, w1.w};
            float xf[8] = {x0.x, x0.y, x0.z, x0.w, x1.x, x1.y, x1.z, x1.w};
#pragma unroll
            for (int i = 0; i < 8; i++)
#pragma unroll
                for (int j = 0; j < 8; j++) acc[i][j] += wf[i] * xf[j];
        }
        __syncthreads();
    }
#pragma unroll
    for (int i = 0; i < 8; i++) {
        int r = ty * 8 + i;
        uint32_t* dst = &g_yb[((size_t)b * 128 + r) * (NN / 2) + (v0 >> 1) + tx * 4];
        uint4 t;
        t.x = pack_bf16(acc[i][0], acc[i][1]);
        t.y = pack_bf16(acc[i][2], acc[i][3]);
        t.z = pack_bf16(acc[i][4], acc[i][5]);
        t.w = pack_bf16(acc[i][6], acc[i][7]);
        *(uint4*)dst = t;
    }
}

// ---------------------------------------------------------------------------
// Kernel B: bf16 mma (cp.async 5-stage + ldmatrix) + FUSED epilogue.
// Mainloop: Z[m=(b,o), n=w] = sum_{s,k} y*adj ; CTA 128x128, K-tile 32.
// m-tile = 2 full batches x 64 o  ->  full epilogue is CTA-local:
//   lin = W_lin.[Z+bm; h], p = PReLU, out2 = [p; h], read = W_read.out2 + br
// ---------------------------------------------------------------------------
#define PITCH   20
#define OPER    (128 * PITCH)         // u32 per operand per stage (2560)
#define STAGEU  (2 * OPER)            // u32 per stage (5120)
#define NSTAGE  5
// epilogue smem (u32 offsets):
#define ZB_OFF  0                     // [128][132] floats = 16896
#define WT_OFF  16896                 // [128][68]  floats = 8704
#define WR_OFF  (WT_OFF + 8704)       // 128
#define RED_OFF (WR_OFF + 128)        // 256
#define BM_OFF  (RED_OFF + 256)       // 64
#define BL_OFF  (BM_OFF + 64)         // 64
#define SMEMB   ((BL_OFF + 64) * 4)   // 104448 bytes (>= NSTAGE*STAGEU*4 = 102400)

__global__ __launch_bounds__(256, 2) void kernB_mma(const float* __restrict__ h,
                                                    const float* __restrict__ Wl,
                                                    const float* __restrict__ bl,
                                                    const float* __restrict__ Wr,
                                                    const float* __restrict__ br,
                                                    const float* __restrict__ bm,
                                                    const float* __restrict__ pa,
                                                    float* __restrict__ out)
{
    extern __shared__ uint32_t smb[];
    const uint32_t smem0 = (uint32_t)__cvta_generic_to_shared(smb);

    const int tid  = threadIdx.x;
    const int wid  = tid >> 5, lane = tid & 31;
    const int wm   = wid & 1;
    const int wn   = wid >> 1;
    const int b0   = blockIdx.x * 2;          // batch pair
    const int m0   = blockIdx.x * 128;
    const int w0   = blockIdx.y * 128;

    float c[4][4][4];
#pragma unroll
    for (int i = 0; i < 4; i++)
#pragma unroll
        for (int j = 0; j < 4; j++)
#pragma unroll
            for (int q = 0; q < 4; q++) c[i][j][q] = 0.0f;

    // ---- loader constants ----
    const int lr  = tid >> 2;
    const int ci  = tid & 3;
    const int mA0 = m0 + lr,       mA1 = m0 + lr + 64;
    const size_t yb0 = ((size_t)(mA0 >> 6) * 128 + (mA0 & 63)) * (NN / 2) + ci * 4;
    const size_t yb1 = ((size_t)(mA1 >> 6) * 128 + (mA1 & 63)) * (NN / 2) + ci * 4;
    const size_t ab0 = (size_t)(w0 + lr) * (NN / 2) + ci * 4;
    const size_t ab1 = (size_t)(w0 + lr + 64) * (NN / 2) + ci * 4;
    const uint32_t dA0 = lr * PITCH + ci * 4, dA1 = (lr + 64) * PITCH + ci * 4;

    auto issue_stage = [&](int it, int st) {
        const int s   = it >> 7;
        const int k0u = (it & 127) << 4;
        const size_t ys = (size_t)s * 64 * (NN / 2) + k0u;
        const size_t as = (size_t)s * NN * (NN / 2) + k0u;
        const uint32_t base = smem0 + st * (STAGEU * 4);
        CP_ASYNC16(base + dA0 * 4,          (const void*)(g_yb + yb0 + ys));
        CP_ASYNC16(base + dA1 * 4,          (const void*)(g_yb + yb1 + ys));
        CP_ASYNC16(base + (OPER + dA0) * 4, (const void*)(g_ab + ab0 + as));
        CP_ASYNC16(base + (OPER + dA1) * 4, (const void*)(g_ab + ab1 + as));
    };

    const uint32_t aoff = (uint32_t)((wm * 64 + (lane & 15)) * PITCH + (lane >> 4) * 4);
    const int bt   = lane >> 3;
    const uint32_t boff = (uint32_t)((wn * 32 + (lane & 7) + ((bt >> 1) * 8)) * PITCH
                                     + (bt & 1) * 4);

    // prologue: stages 0..3
    issue_stage(0, 0); CP_COMMIT();
    issue_stage(1, 1); CP_COMMIT();
    issue_stage(2, 2); CP_COMMIT();
    issue_stage(3, 3); CP_COMMIT();

    for (int it = 0; it < 256; ++it) {
        CP_WAIT3();
        __syncthreads();
        if (it + 4 < 256) issue_stage(it + 4, (it + 4) % NSTAGE);
        CP_COMMIT();

        const uint32_t Ab = smem0 + (it % NSTAGE) * (STAGEU * 4);
        const uint32_t Bb = Ab + OPER * 4;

#pragma unroll
        for (int kk = 0; kk < 2; kk++) {
            uint32_t a[4][4], bfr[4][2];
#pragma unroll
            for (int mi = 0; mi < 4; mi++) {
                uint32_t ad = Ab + (aoff + mi * 16 * PITCH + kk * 8) * 4;
                LDSM_X4(a[mi][0], a[mi][1], a[mi][2], a[mi][3], ad);
            }
#pragma unroll
            for (int nj = 0; nj < 2; nj++) {
                uint32_t bd = Bb + (boff + nj * 16 * PITCH + kk * 8) * 4;
                LDSM_X4(bfr[nj * 2][0], bfr[nj * 2][1],
                        bfr[nj * 2 + 1][0], bfr[nj * 2 + 1][1], bd);
            }
#pragma unroll
            for (int mi = 0; mi < 4; mi++)
#pragma unroll
                for (int ni = 0; ni < 4; ni++)
                    MMA_BF16(c[mi][ni], a[mi], bfr[ni]);
        }
    }

    // ================== fused epilogue ==================
    __syncthreads();                 // mainloop smem reads done; safe to reuse

    float* Zbf  = (float*)(smb + ZB_OFF);    // [128][132]
    float* Wtf  = (float*)(smb + WT_OFF);    // [k=128][o=64] pitch 68
    float* wr_s = (float*)(smb + WR_OFF);
    float* redf = (float*)(smb + RED_OFF);   // [2][128]
    float* bm_s = (float*)(smb + BM_OFF);
    float* bl_s = (float*)(smb + BL_OFF);

    // store fragments -> Zbf (rows: wm*64 + ..., cols: wn*32 + ...)
    {
        const int r = lane >> 2, cc2 = (lane & 3) * 2;
#pragma unroll
        for (int mi = 0; mi < 4; mi++) {
            const int row = wm * 64 + mi * 16 + r;
#pragma unroll
            for (int ni = 0; ni < 4; ni++) {
                const int col = wn * 32 + ni * 8 + cc2;
                Zbf[row * 132 + col]           = c[mi][ni][0];
                Zbf[row * 132 + col + 1]       = c[mi][ni][1];
                Zbf[(row + 8) * 132 + col]     = c[mi][ni][2];
                Zbf[(row + 8) * 132 + col + 1] = c[mi][ni][3];
            }
        }
    }
    // load W_lin transposed, wr, bm, bl; zero red
    for (int idx = tid; idx < 8192; idx += 256) {
        int o = idx >> 7, k = idx & 127;
        Wtf[k * 68 + o] = Wl[o * 128 + k];
    }
    if (tid < 128) wr_s[tid] = Wr[tid];
    if (tid < 64)  { bm_s[tid] = bm[tid]; bl_s[tid] = bl[tid]; }
    redf[tid] = 0.0f;
    __syncthreads();

    const int ty = tid >> 4, tx = tid & 15;
    float acc2[2][4][8];
#pragma unroll
    for (int i = 0; i < 4; i++) {
        float bv = bl_s[ty * 4 + i];
#pragma unroll
        for (int j = 0; j < 8; j++) { acc2[0][i][j] = bv; acc2[1][i][j] = bv; }
    }

    // ---- k-half 1: Z (+bm) from Zbf ----
#pragma unroll 4
    for (int k = 0; k < 64; k++) {
        float4 wv = *(const float4*)&Wtf[k * 68 + ty * 4];
        float wf[4] = {wv.x, wv.y, wv.z, wv.w};
        float bmk = bm_s[k];
#pragma unroll
        for (int bb = 0; bb < 2; bb++) {
            float4 z0 = *(const float4*)&Zbf[(bb * 64 + k) * 132 + tx * 8];
            float4 z1 = *(const float4*)&Zbf[(bb * 64 + k) * 132 + tx * 8 + 4];
            float in[8] = {z0.x + bmk, z0.y + bmk, z0.z + bmk, z0.w + bmk,
                           z1.x + bmk, z1.y + bmk, z1.z + bmk, z1.w + bmk};
#pragma unroll
            for (int i = 0; i < 4; i++)
#pragma unroll
                for (int j = 0; j < 8; j++) acc2[bb][i][j] += wf[i] * in[j];
        }
    }
    __syncthreads();   // Zbf Z-data consumed

    // ---- stage h for both batches into Zbf ----
    for (int idx = tid; idx < 16384; idx += 256) {
        int row = idx >> 7, v = idx & 127;
        Zbf[row * 132 + v] =
            h[((size_t)(b0 + (row >> 6)) * DM + (row & 63)) * NN + w0 + v];
    }
    __syncthreads();

    // ---- k-half 2: h ----
#pragma unroll 4
    for (int k = 0; k < 64; k++) {
        float4 wv = *(const float4*)&Wtf[(64 + k) * 68 + ty * 4];
        float wf[4] = {wv.x, wv.y, wv.z, wv.w};
#pragma unroll
        for (int bb = 0; bb < 2; bb++) {
            float4 z0 = *(const float4*)&Zbf[(bb * 64 + k) * 132 + tx * 8];
            float4 z1 = *(const float4*)&Zbf[(bb * 64 + k) * 132 + tx * 8 + 4];
            float in[8] = {z0.x, z0.y, z0.z, z0.w, z1.x, z1.y, z1.z, z1.w};
#pragma unroll
            for (int i = 0; i < 4; i++)
#pragma unroll
                for (int j = 0; j < 8; j++) acc2[bb][i][j] += wf[i] * in[j];
        }
    }

    // ---- tail: PReLU, out2, read reduction ----
    const float slope = pa[0];
    float* out2 = out + (size_t)NB * NN;
#pragma unroll
    for (int bb = 0; bb < 2; bb++) {
        const int b = b0 + bb;
        float part[8];
#pragma unroll
        for (int j = 0; j < 8; j++) part[j] = 0.0f;
#pragma unroll
        for (int i = 0; i < 4; i++) {
            const int o = ty * 4 + i;
            const float wro = wr_s[o], wrh = wr_s[64 + o];
            float p[8], hv[8];
#pragma unroll
            for (int j = 0; j < 8; j++) {
                float v = acc2[bb][i][j];
                p[j] = (v >= 0.0f) ? v : slope * v;
                part[j] += wro * p[j];
                hv[j] = Zbf[(bb * 64 + o) * 132 + tx * 8 + j];
                part[j] += wrh * hv[j];
            }
            float* dst = &out2[((size_t)b * 128 + o) * NN + w0 + tx * 8];
            *(float4*)dst       = make_float4(p[0], p[1], p[2], p[3]);
            *(float4*)(dst + 4) = make_float4(p[4], p[5], p[6], p[7]);
            float* dsth = &out2[((size_t)b * 128 + 64 + o) * NN + w0 + tx * 8];
            *(float4*)dsth       = make_float4(hv[0], hv[1], hv[2], hv[3]);
            *(float4*)(dsth + 4) = make_float4(hv[4], hv[5], hv[6], hv[7]);
        }
#pragma unroll
        for (int j = 0; j < 8; j++)
            atomicAdd(&redf[bb * 128 + tx * 8 + j], part[j]);
    }
    __syncthreads();
    {
        const int bb = tid >> 7, v = tid & 127;
        out[(size_t)(b0 + bb) * NN + w0 + v] = redf[tid] + br[0];
    }
}

// ---------------------------------------------------------------------------
extern "C" void kernel_launch(void* const* d_in, const int* in_sizes, int n_in,
                              void* d_out, int out_size)
{
    const float* x   = (const float*)d_in[0];
    const float* h   = (const float*)d_in[1];
    const float* adj = (const float*)d_in[2];
    const float* Wm  = (const float*)d_in[3];
    const float* bm  = (const float*)d_in[4];
    const float* Wl  = (const float*)d_in[5];
    const float* bl  = (const float*)d_in[6];
    const float* Wr  = (const float*)d_in[7];
    const float* br  = (const float*)d_in[8];
    const float* pa  = (const float*)d_in[9];
    float* out = (float*)d_out;

    cudaFuncSetAttribute(kernB_mma, cudaFuncAttributeMaxDynamicSharedMemorySize, SMEMB);

    dim3 gridA(NN / 128, NB);
    kernP<<<2 * NN * (NN / 2) / (256 * 4), 256>>>(adj);
    kernA<<<gridA, 256>>>(x, h, Wm);
    kernB_mma<<<dim3(2048 / 128, NN / 128), 256, SMEMB>>>(h, Wl, bl, Wr, br, bm, pa, out);
}

// round 12
// speedup vs baseline: 9.8316x; 1.1224x over previous
#include <cuda_runtime.h>
#include <cuda_bf16.h>
#include <cstdint>

#define NB   32
#define NN   4096
#define DM   64

// scratch (allocation-free: device globals)
__device__ uint32_t g_yb[NB * 2 * DM * (NN / 2)];  // y bf16x2: [b][s*64+o][k/2]  32 MB
__device__ uint32_t g_ab[2 * NN * (NN / 2)];       // adj bf16x2: [s][w][k/2]     67 MB

__device__ __forceinline__ uint32_t pack_bf16(float lo, float hi) {
    uint32_t r;
    asm("cvt.rn.bf16x2.f32 %0, %1, %2;" : "=r"(r) : "f"(hi), "f"(lo));
    return r;
}

#define MMA_BF16(c, a, b)                                                    \
    asm volatile("mma.sync.aligned.m16n8k16.row.col.f32.bf16.bf16.f32 "      \
                 "{%0,%1,%2,%3}, {%4,%5,%6,%7}, {%8,%9}, {%0,%1,%2,%3};"     \
                 : "+f"((c)[0]), "+f"((c)[1]), "+f"((c)[2]), "+f"((c)[3])    \
                 : "r"((a)[0]), "r"((a)[1]), "r"((a)[2]), "r"((a)[3]),       \
                   "r"((b)[0]), "r"((b)[1]))

#define LDSM_X4(r0, r1, r2, r3, addr)                                        \
    asm volatile("ldmatrix.sync.aligned.m8n8.x4.shared.b16 {%0,%1,%2,%3}, [%4];" \
                 : "=r"(r0), "=r"(r1), "=r"(r2), "=r"(r3) : "r"(addr))

#define CP_ASYNC16(dst, src)                                                 \
    asm volatile("cp.async.cg.shared.global [%0], [%1], 16;"                 \
                 :: "r"(dst), "l"(src) : "memory")
#define CP_COMMIT()  asm volatile("cp.async.commit_group;" ::: "memory")
#define CP_WAIT3()   asm volatile("cp.async.wait_group 3;" ::: "memory")

// ---------------------------------------------------------------------------
// Kernel P: adj float -> bf16 (g_ab)
// ---------------------------------------------------------------------------
__global__ __launch_bounds__(256) void kernP(const float* __restrict__ adj)
{
    const size_t u = ((size_t)blockIdx.x * 256 + threadIdx.x) * 4;
    const float4* s = (const float4*)(adj + u * 2);
    float4 v0 = s[0], v1 = s[1];
    uint4 t;
    t.x = pack_bf16(v0.x, v0.y); t.y = pack_bf16(v0.z, v0.w);
    t.z = pack_bf16(v1.x, v1.y); t.w = pack_bf16(v1.z, v1.w);
    *(uint4*)(g_ab + u) = t;
}

// ---------------------------------------------------------------------------
// Kernel A (bf16 mma): y[b, r=s*64+o, v] = sum_c W_mlp[o, s*65+c] * xin[b,c,v]
// A = W [r][c] k-major bf16, B = xin^T [v][c] k-major bf16 (SMEM transpose).
// c padded 65 -> 80 (5 k16 steps, pads zeroed). Output packed bf16x2 -> g_yb.
// ---------------------------------------------------------------------------
#define PA 44   // u32 pitch per row (176B, 16B-aligned)

__global__ __launch_bounds__(256, 2) void kernA_mma(const float* __restrict__ x,
                                                    const float* __restrict__ h,
                                                    const float* __restrict__ Wm)
{
    __shared__ uint32_t Ws[128 * PA];   // bf16 [r][c]
    __shared__ uint32_t Xs[128 * PA];   // bf16 [v][c]
    const int tid  = threadIdx.x;
    const int wid  = tid >> 5, lane = tid & 31;
    const int wm   = wid & 1, wn = wid >> 1;
    const int b    = blockIdx.y;
    const int v0   = blockIdx.x * 128;

    // zero everything (covers the k-pad columns; avoids NaN garbage)
    for (int i = tid; i < 128 * PA; i += 256) { Ws[i] = 0u; Xs[i] = 0u; }
    __syncthreads();

    uint16_t* Wh = (uint16_t*)Ws;
    uint16_t* Xh = (uint16_t*)Xs;

    // fill W: r = s*64+o rows, c columns (coalesced-ish over c)
    for (int idx = tid; idx < 128 * 65; idx += 256) {
        int r = idx / 65, c = idx - r * 65;
        int s = r >> 6, o = r & 63;
        float w = Wm[o * 130 + s * 65 + c];
        Wh[r * (PA * 2) + c] = (uint16_t)pack_bf16(w, 0.0f);
    }
    // fill xin^T: read xin[c][v] coalesced in v, store transposed [v][c]
    for (int idx = tid; idx < 65 * 128; idx += 256) {
        int c = idx >> 7, v = idx & 127;
        float val;
        if (c == 0) val = x[(size_t)b * NN + v0 + v];
        else        val = h[((size_t)b * DM + (c - 1)) * NN + v0 + v];
        Xh[v * (PA * 2) + c] = (uint16_t)pack_bf16(val, 0.0f);
    }
    __syncthreads();

    float c[4][4][4];
#pragma unroll
    for (int i = 0; i < 4; i++)
#pragma unroll
        for (int j = 0; j < 4; j++)
#pragma unroll
            for (int q = 0; q < 4; q++) c[i][j][q] = 0.0f;

    const uint32_t Abase = (uint32_t)__cvta_generic_to_shared(Ws);
    const uint32_t Bbase = (uint32_t)__cvta_generic_to_shared(Xs);
    const uint32_t aoff  = (uint32_t)((wm * 64 + (lane & 15)) * PA + (lane >> 4) * 4);
    const int bt = lane >> 3;
    const uint32_t boff  = (uint32_t)((wn * 32 + (lane & 7) + ((bt >> 1) * 8)) * PA
                                      + (bt & 1) * 4);

#pragma unroll
    for (int kk = 0; kk < 5; kk++) {
        uint32_t a[4][4], bfr[4][2];
#pragma unroll
        for (int mi = 0; mi < 4; mi++) {
            uint32_t ad = Abase + (aoff + mi * 16 * PA + kk * 8) * 4;
            LDSM_X4(a[mi][0], a[mi][1], a[mi][2], a[mi][3], ad);
        }
#pragma unroll
        for (int nj = 0; nj < 2; nj++) {
            uint32_t bd = Bbase + (boff + nj * 16 * PA + kk * 8) * 4;
            LDSM_X4(bfr[nj * 2][0], bfr[nj * 2][1],
                    bfr[nj * 2 + 1][0], bfr[nj * 2 + 1][1], bd);
        }
#pragma unroll
        for (int mi = 0; mi < 4; mi++)
#pragma unroll
            for (int ni = 0; ni < 4; ni++)
                MMA_BF16(c[mi][ni], a[mi], bfr[ni]);
    }

    // store: frag cols are adjacent v pairs -> bf16x2 direct to g_yb
    const int r2 = lane >> 2, cc2 = lane & 3;
#pragma unroll
    for (int mi = 0; mi < 4; mi++) {
        const int mrow = wm * 64 + mi * 16 + r2;
#pragma unroll
        for (int ni = 0; ni < 4; ni++) {
            const int vu = (v0 >> 1) + wn * 16 + ni * 4 + cc2;
            g_yb[((size_t)b * 128 + mrow) * (NN / 2) + vu] =
                pack_bf16(c[mi][ni][0], c[mi][ni][1]);
            g_yb[((size_t)b * 128 + mrow + 8) * (NN / 2) + vu] =
                pack_bf16(c[mi][ni][2], c[mi][ni][3]);
        }
    }
}

// ---------------------------------------------------------------------------
// Kernel B: bf16 mma (cp.async 5-stage + ldmatrix) + FUSED epilogue.
// ---------------------------------------------------------------------------
#define PITCH   20
#define OPER    (128 * PITCH)
#define STAGEU  (2 * OPER)
#define NSTAGE  5
#define ZB_OFF  0
#define WT_OFF  16896
#define WR_OFF  (WT_OFF + 8704)
#define RED_OFF (WR_OFF + 128)
#define BM_OFF  (RED_OFF + 256)
#define BL_OFF  (BM_OFF + 64)
#define SMEMB   ((BL_OFF + 64) * 4)

__global__ __launch_bounds__(256, 2) void kernB_mma(const float* __restrict__ h,
                                                    const float* __restrict__ Wl,
                                                    const float* __restrict__ bl,
                                                    const float* __restrict__ Wr,
                                                    const float* __restrict__ br,
                                                    const float* __restrict__ bm,
                                                    const float* __restrict__ pa,
                                                    float* __restrict__ out)
{
    extern __shared__ uint32_t smb[];
    const uint32_t smem0 = (uint32_t)__cvta_generic_to_shared(smb);

    const int tid  = threadIdx.x;
    const int wid  = tid >> 5, lane = tid & 31;
    const int wm   = wid & 1;
    const int wn   = wid >> 1;
    const int b0   = blockIdx.x * 2;
    const int m0   = blockIdx.x * 128;
    const int w0   = blockIdx.y * 128;

    float c[4][4][4];
#pragma unroll
    for (int i = 0; i < 4; i++)
#pragma unroll
        for (int j = 0; j < 4; j++)
#pragma unroll
            for (int q = 0; q < 4; q++) c[i][j][q] = 0.0f;

    const int lr  = tid >> 2;
    const int ci  = tid & 3;
    const int mA0 = m0 + lr,       mA1 = m0 + lr + 64;
    const size_t yb0 = ((size_t)(mA0 >> 6) * 128 + (mA0 & 63)) * (NN / 2) + ci * 4;
    const size_t yb1 = ((size_t)(mA1 >> 6) * 128 + (mA1 & 63)) * (NN / 2) + ci * 4;
    const size_t ab0 = (size_t)(w0 + lr) * (NN / 2) + ci * 4;
    const size_t ab1 = (size_t)(w0 + lr + 64) * (NN / 2) + ci * 4;
    const uint32_t dA0 = lr * PITCH + ci * 4, dA1 = (lr + 64) * PITCH + ci * 4;

    auto issue_stage = [&](int it, int st) {
        const int s   = it >> 7;
        const int k0u = (it & 127) << 4;
        const size_t ys = (size_t)s * 64 * (NN / 2) + k0u;
        const size_t as = (size_t)s * NN * (NN / 2) + k0u;
        const uint32_t base = smem0 + st * (STAGEU * 4);
        CP_ASYNC16(base + dA0 * 4,          (const void*)(g_yb + yb0 + ys));
        CP_ASYNC16(base + dA1 * 4,          (const void*)(g_yb + yb1 + ys));
        CP_ASYNC16(base + (OPER + dA0) * 4, (const void*)(g_ab + ab0 + as));
        CP_ASYNC16(base + (OPER + dA1) * 4, (const void*)(g_ab + ab1 + as));
    };

    const uint32_t aoff = (uint32_t)((wm * 64 + (lane & 15)) * PITCH + (lane >> 4) * 4);
    const int bt   = lane >> 3;
    const uint32_t boff = (uint32_t)((wn * 32 + (lane & 7) + ((bt >> 1) * 8)) * PITCH
                                     + (bt & 1) * 4);

    issue_stage(0, 0); CP_COMMIT();
    issue_stage(1, 1); CP_COMMIT();
    issue_stage(2, 2); CP_COMMIT();
    issue_stage(3, 3); CP_COMMIT();

    for (int it = 0; it < 256; ++it) {
        CP_WAIT3();
        __syncthreads();
        if (it + 4 < 256) issue_stage(it + 4, (it + 4) % NSTAGE);
        CP_COMMIT();

        const uint32_t Ab = smem0 + (it % NSTAGE) * (STAGEU * 4);
        const uint32_t Bb = Ab + OPER * 4;

#pragma unroll
        for (int kk = 0; kk < 2; kk++) {
            uint32_t a[4][4], bfr[4][2];
#pragma unroll
            for (int mi = 0; mi < 4; mi++) {
                uint32_t ad = Ab + (aoff + mi * 16 * PITCH + kk * 8) * 4;
                LDSM_X4(a[mi][0], a[mi][1], a[mi][2], a[mi][3], ad);
            }
#pragma unroll
            for (int nj = 0; nj < 2; nj++) {
                uint32_t bd = Bb + (boff + nj * 16 * PITCH + kk * 8) * 4;
                LDSM_X4(bfr[nj * 2][0], bfr[nj * 2][1],
                        bfr[nj * 2 + 1][0], bfr[nj * 2 + 1][1], bd);
            }
#pragma unroll
            for (int mi = 0; mi < 4; mi++)
#pragma unroll
                for (int ni = 0; ni < 4; ni++)
                    MMA_BF16(c[mi][ni], a[mi], bfr[ni]);
        }
    }

    // ================== fused epilogue ==================
    __syncthreads();

    float* Zbf  = (float*)(smb + ZB_OFF);
    float* Wtf  = (float*)(smb + WT_OFF);
    float* wr_s = (float*)(smb + WR_OFF);
    float* redf = (float*)(smb + RED_OFF);
    float* bm_s = (float*)(smb + BM_OFF);
    float* bl_s = (float*)(smb + BL_OFF);

    {
        const int r = lane >> 2, cc2 = (lane & 3) * 2;
#pragma unroll
        for (int mi = 0; mi < 4; mi++) {
            const int row = wm * 64 + mi * 16 + r;
#pragma unroll
            for (int ni = 0; ni < 4; ni++) {
                const int col = wn * 32 + ni * 8 + cc2;
                Zbf[row * 132 + col]           = c[mi][ni][0];
                Zbf[row * 132 + col + 1]       = c[mi][ni][1];
                Zbf[(row + 8) * 132 + col]     = c[mi][ni][2];
                Zbf[(row + 8) * 132 + col + 1] = c[mi][ni][3];
            }
        }
    }
    for (int idx = tid; idx < 8192; idx += 256) {
        int o = idx >> 7, k = idx & 127;
        Wtf[k * 68 + o] = Wl[o * 128 + k];
    }
    if (tid < 128) wr_s[tid] = Wr[tid];
    if (tid < 64)  { bm_s[tid] = bm[tid]; bl_s[tid] = bl[tid]; }
    redf[tid] = 0.0f;
    __syncthreads();

    const int ty = tid >> 4, tx = tid & 15;
    float acc2[2][4][8];
#pragma unroll
    for (int i = 0; i < 4; i++) {
        float bv = bl_s[ty * 4 + i];
#pragma unroll
        for (int j = 0; j < 8; j++) { acc2[0][i][j] = bv; acc2[1][i][j] = bv; }
    }

#pragma unroll 4
    for (int k = 0; k < 64; k++) {
        float4 wv = *(const float4*)&Wtf[k * 68 + ty * 4];
        float wf[4] = {wv.x, wv.y, wv.z, wv.w};
        float bmk = bm_s[k];
#pragma unroll
        for (int bb = 0; bb < 2; bb++) {
            float4 z0 = *(const float4*)&Zbf[(bb * 64 + k) * 132 + tx * 8];
            float4 z1 = *(const float4*)&Zbf[(bb * 64 + k) * 132 + tx * 8 + 4];
            float in[8] = {z0.x + bmk, z0.y + bmk, z0.z + bmk, z0.w + bmk,
                           z1.x + bmk, z1.y + bmk, z1.z + bmk, z1.w + bmk};
#pragma unroll
            for (int i = 0; i < 4; i++)
#pragma unroll
                for (int j = 0; j < 8; j++) acc2[bb][i][j] += wf[i] * in[j];
        }
    }
    __syncthreads();

    for (int idx = tid; idx < 16384; idx += 256) {
        int row = idx >> 7, v = idx & 127;
        Zbf[row * 132 + v] =
            h[((size_t)(b0 + (row >> 6)) * DM + (row & 63)) * NN + w0 + v];
    }
    __syncthreads();

#pragma unroll 4
    for (int k = 0; k < 64; k++) {
        float4 wv = *(const float4*)&Wtf[(64 + k) * 68 + ty * 4];
        float wf[4] = {wv.x, wv.y, wv.z, wv.w};
#pragma unroll
        for (int bb = 0; bb < 2; bb++) {
            float4 z0 = *(const float4*)&Zbf[(bb * 64 + k) * 132 + tx * 8];
            float4 z1 = *(const float4*)&Zbf[(bb * 64 + k) * 132 + tx * 8 + 4];
            float in[8] = {z0.x, z0.y, z0.z, z0.w, z1.x, z1.y, z1.z, z1.w};
#pragma unroll
            for (int i = 0; i < 4; i++)
#pragma unroll
                for (int j = 0; j < 8; j++) acc2[bb][i][j] += wf[i] * in[j];
        }
    }

    const float slope = pa[0];
    float* out2 = out + (size_t)NB * NN;
#pragma unroll
    for (int bb = 0; bb < 2; bb++) {
        const int b = b0 + bb;
        float part[8];
#pragma unroll
        for (int j = 0; j < 8; j++) part[j] = 0.0f;
#pragma unroll
        for (int i = 0; i < 4; i++) {
            const int o = ty * 4 + i;
            const float wro = wr_s[o], wrh = wr_s[64 + o];
            float p[8], hv[8];
#pragma unroll
            for (int j = 0; j < 8; j++) {
                float v = acc2[bb][i][j];
                p[j] = (v >= 0.0f) ? v : slope * v;
                part[j] += wro * p[j];
                hv[j] = Zbf[(bb * 64 + o) * 132 + tx * 8 + j];
                part[j] += wrh * hv[j];
            }
            float* dst = &out2[((size_t)b * 128 + o) * NN + w0 + tx * 8];
            *(float4*)dst       = make_float4(p[0], p[1], p[2], p[3]);
            *(float4*)(dst + 4) = make_float4(p[4], p[5], p[6], p[7]);
            float* dsth = &out2[((size_t)b * 128 + 64 + o) * NN + w0 + tx * 8];
            *(float4*)dsth       = make_float4(hv[0], hv[1], hv[2], hv[3]);
            *(float4*)(dsth + 4) = make_float4(hv[4], hv[5], hv[6], hv[7]);
        }
#pragma unroll
        for (int j = 0; j < 8; j++)
            atomicAdd(&redf[bb * 128 + tx * 8 + j], part[j]);
    }
    __syncthreads();
    {
        const int bb = tid >> 7, v = tid & 127;
        out[(size_t)(b0 + bb) * NN + w0 + v] = redf[tid] + br[0];
    }
}

// ---------------------------------------------------------------------------
extern "C" void kernel_launch(void* const* d_in, const int* in_sizes, int n_in,
                              void* d_out, int out_size)
{
    const float* x   = (const float*)d_in[0];
    const float* h   = (const float*)d_in[1];
    const float* adj = (const float*)d_in[2];
    const float* Wm  = (const float*)d_in[3];
    const float* bm  = (const float*)d_in[4];
    const float* Wl  = (const float*)d_in[5];
    const float* bl  = (const float*)d_in[6];
    const float* Wr  = (const float*)d_in[7];
    const float* br  = (const float*)d_in[8];
    const float* pa  = (const float*)d_in[9];
    float* out = (float*)d_out;

    cudaFuncSetAttribute(kernB_mma, cudaFuncAttributeMaxDynamicSharedMemorySize, SMEMB);

    kernP<<<2 * NN * (NN / 2) / (256 * 4), 256>>>(adj);
    kernA_mma<<<dim3(NN / 128, NB), 256>>>(x, h, Wm);
    kernB_mma<<<dim3(2048 / 128, NN / 128), 256, SMEMB>>>(h, Wl, bl, Wr, br, bm, pa, out);
}